// round 4
// baseline (speedup 1.0000x reference)
#include <cuda_runtime.h>

// IndRNN: out[b,t,r] = relu(xp[b,t,r] + u[r]*h_prev), xp = x@W + bias, h0 = 1
// Kernel 1: fp32 SGEMM (M=65536, N=512, K=512) + bias -> writes xp into d_out
// Kernel 2: in-place per-(b,r) scan over t with software-pipelined loads

#define BM 128
#define BN 64
#define BK 16
#define TM 8
#define TN 4

__global__ __launch_bounds__(256) void indrnn_gemm_bias(
    const float* __restrict__ A,     // [65536, 512]
    const float* __restrict__ W,     // [512, 512]
    const float* __restrict__ bias,  // [512]
    float* __restrict__ C)           // [65536, 512]
{
    const int K = 512;
    const int N = 512;

    __shared__ float As[BK][BM];   // [k][m]
    __shared__ float Ws[BK][BN];   // [k][n]

    const int bm = blockIdx.y * BM;
    const int bn = blockIdx.x * BN;
    const int tid = (int)threadIdx.x;

    const int ty = tid >> 4;   // 0..15 -> 8 m-rows each
    const int tx = tid & 15;   // 0..15 -> 4 n-cols each

    // global load mapping
    const int arow = tid >> 2;   // 0..63 (two rows per thread: arow, arow+64)
    const int ak4  = tid & 3;    // float4 index along K within BK
    const int wrow = tid >> 4;   // 0..15 (k within tile)
    const int wc4  = tid & 15;   // float4 index along N within BN

    float acc[TM][TN];
    #pragma unroll
    for (int i = 0; i < TM; i++)
        #pragma unroll
        for (int j = 0; j < TN; j++)
            acc[i][j] = 0.0f;

    const float* Aptr0 = A + (size_t)(bm + arow) * K + ak4 * 4;
    const float* Aptr1 = Aptr0 + (size_t)64 * K;
    const float* Wptr  = W + (size_t)wrow * N + bn + wc4 * 4;

    for (int k0 = 0; k0 < K; k0 += BK) {
        float4 a0 = *(const float4*)(Aptr0 + k0);
        float4 a1 = *(const float4*)(Aptr1 + k0);
        float4 w0 = *(const float4*)(Wptr + (size_t)k0 * N);

        __syncthreads();  // protect previous tile's reads before overwrite

        const int kb = ak4 * 4;
        As[kb + 0][arow] = a0.x;
        As[kb + 1][arow] = a0.y;
        As[kb + 2][arow] = a0.z;
        As[kb + 3][arow] = a0.w;
        As[kb + 0][arow + 64] = a1.x;
        As[kb + 1][arow + 64] = a1.y;
        As[kb + 2][arow + 64] = a1.z;
        As[kb + 3][arow + 64] = a1.w;
        *(float4*)&Ws[wrow][wc4 * 4] = w0;

        __syncthreads();

        #pragma unroll
        for (int kk = 0; kk < BK; kk++) {
            float4 ra0 = *(const float4*)&As[kk][ty * TM];
            float4 ra1 = *(const float4*)&As[kk][ty * TM + 4];
            float4 rb  = *(const float4*)&Ws[kk][tx * TN];
            float a[TM] = {ra0.x, ra0.y, ra0.z, ra0.w, ra1.x, ra1.y, ra1.z, ra1.w};
            float bv[TN] = {rb.x, rb.y, rb.z, rb.w};
            #pragma unroll
            for (int i = 0; i < TM; i++)
                #pragma unroll
                for (int j = 0; j < TN; j++)
                    acc[i][j] = fmaf(a[i], bv[j], acc[i][j]);
        }
    }

    // epilogue: add bias, store
    float4 bb = *(const float4*)&bias[bn + tx * TN];
    #pragma unroll
    for (int i = 0; i < TM; i++) {
        float4 o;
        o.x = acc[i][0] + bb.x;
        o.y = acc[i][1] + bb.y;
        o.z = acc[i][2] + bb.z;
        o.w = acc[i][3] + bb.w;
        *(float4*)&C[(size_t)(bm + ty * TM + i) * N + bn + tx * TN] = o;
    }
}

// One thread per (b, r). Loads for step t don't depend on h, so batch 16
// loads ahead of the serial FMA/relu chain -> MLP=16 per thread.
__global__ __launch_bounds__(256) void indrnn_scan(
    float* __restrict__ xp,         // [64, 1024, 512], in-place
    const float* __restrict__ u)    // [512]
{
    const int T = 1024;
    const int R = 512;
    int idx = blockIdx.x * blockDim.x + threadIdx.x;  // 0..32767
    int b = idx >> 9;
    int r = idx & 511;

    float uu = u[r];
    float h = 1.0f;
    float* p = xp + (size_t)b * T * R + r;

    #pragma unroll 1
    for (int t0 = 0; t0 < T; t0 += 16) {
        float v[16];
        #pragma unroll
        for (int j = 0; j < 16; j++)
            v[j] = p[(t0 + j) * R];
        #pragma unroll
        for (int j = 0; j < 16; j++) {
            h = fmaxf(fmaf(uu, h, v[j]), 0.0f);
            v[j] = h;
        }
        #pragma unroll
        for (int j = 0; j < 16; j++)
            p[(t0 + j) * R] = v[j];
    }
}

extern "C" void kernel_launch(void* const* d_in, const int* in_sizes, int n_in,
                              void* d_out, int out_size)
{
    const float* x  = (const float*)d_in[0];  // [64,1024,512]
    const float* W  = (const float*)d_in[1];  // [512,512]
    const float* u  = (const float*)d_in[2];  // [512]
    const float* b  = (const float*)d_in[3];  // [512]
    float* out = (float*)d_out;               // [64,1024,512]

    (void)in_sizes; (void)n_in; (void)out_size;

    // GEMM: M = 64*1024 = 65536 rows
    dim3 ggrid(512 / BN, 65536 / BM);  // (8, 512)
    indrnn_gemm_bias<<<ggrid, 256>>>(x, W, b, out);

    // Scan: 64*512 = 32768 threads
    indrnn_scan<<<128, 256>>>(out, u);
}

// round 6
// speedup vs baseline: 1.5546x; 1.5546x over previous
#include <cuda_runtime.h>
#include <cuda_bf16.h>
#include <cstdint>

// ============================================================
// IndRNN on GB300 (base-PTX tensor path; tcgen05 unavailable in
// this toolchain's compute_103 PTX stage):
//   xp = x @ W     -> split-bf16 mma.sync (HMMA) GEMM, fp32 accum
//   out = scan(relu(xp_t + b + u*h))
// ============================================================

// Transposed + hi/lo split W scratch ([n][k], k contiguous)
__device__ __nv_bfloat16 g_Wt_hi[512 * 512];
__device__ __nv_bfloat16 g_Wt_lo[512 * 512];

__device__ __forceinline__ uint32_t smem_u32(const void* p) {
    uint32_t a;
    asm("{ .reg .u64 t; cvta.to.shared.u64 t, %1; cvt.u32.u64 %0, t; }"
        : "=r"(a) : "l"(p));
    return a;
}

__device__ __forceinline__ void ldm_x4(uint32_t r[4], uint32_t addr) {
    asm volatile("ldmatrix.sync.aligned.m8n8.x4.shared.b16 {%0,%1,%2,%3}, [%4];"
                 : "=r"(r[0]), "=r"(r[1]), "=r"(r[2]), "=r"(r[3]) : "r"(addr));
}

__device__ __forceinline__ void mma_bf16(float c[4], const uint32_t a[4],
                                         const uint32_t b[2]) {
    asm volatile(
        "mma.sync.aligned.m16n8k16.row.col.f32.bf16.bf16.f32 "
        "{%0,%1,%2,%3}, {%4,%5,%6,%7}, {%8,%9}, {%0,%1,%2,%3};"
        : "+f"(c[0]), "+f"(c[1]), "+f"(c[2]), "+f"(c[3])
        : "r"(a[0]), "r"(a[1]), "r"(a[2]), "r"(a[3]), "r"(b[0]), "r"(b[1]));
}

// ---------------- W prepass: transpose + hi/lo split ----------------
__global__ __launch_bounds__(256) void conv_w(const float* __restrict__ W) {
    int idx = blockIdx.x * blockDim.x + threadIdx.x;  // 0..262143
    int n = idx >> 9;
    int k = idx & 511;
    float w = W[k * 512 + n];
    __nv_bfloat16 h = __float2bfloat16(w);
    g_Wt_hi[idx] = h;
    g_Wt_lo[idx] = __float2bfloat16(w - __bfloat162float(h));
}

// ---------------- HMMA GEMM: C[65536,512] = A[65536,512] @ W ----------------
// CTA tile 128x128, BK=32, double-buffered smem + register prefetch.
// SMEM rows padded to 80B (stride 40 bf16) -> conflict-free ldmatrix.

#define ROWB     80                       // bytes per smem row (32 bf16 + pad)
#define MAT_SZ   (128 * ROWB)             // 10240
#define OFF_AHI  0
#define OFF_ALO  (1 * MAT_SZ)
#define OFF_BHI  (2 * MAT_SZ)
#define OFF_BLO  (3 * MAT_SZ)
#define STAGE_SZ (4 * MAT_SZ)             // 40960
#define GEMM_SMEM (2 * STAGE_SZ)          // 81920

__global__ __launch_bounds__(256, 1) void indrnn_gemm_mma(
    const float* __restrict__ A,   // [65536, 512]
    float* __restrict__ C)         // [65536, 512]
{
    extern __shared__ char smem[];
    const uint32_t sb = smem_u32(smem);
    const int tid = (int)threadIdx.x;
    const int wid = tid >> 5;
    const int lane = tid & 31;

    const int bn = blockIdx.x * 128;   // 4 n-tiles (fastest -> A L2 reuse)
    const int bm = blockIdx.y * 128;   // 512 m-tiles

    const int wm = (wid & 1) * 64;     // warp m-offset within CTA tile
    const int wn = (wid >> 1) * 32;    // warp n-offset

    // staging indices: each thread owns 16 consecutive k of one row
    const int srow = tid >> 1;         // 0..127
    const int shalf = tid & 1;         // 0 or 1 (k 0-15 / 16-31)

    const float* aptr = A + (size_t)(bm + srow) * 512 + shalf * 16;
    const __nv_bfloat16* bptr_h = g_Wt_hi + (size_t)(bn + srow) * 512 + shalf * 16;
    const __nv_bfloat16* bptr_l = g_Wt_lo + (size_t)(bn + srow) * 512 + shalf * 16;
    const uint32_t swoff = (uint32_t)(srow * ROWB + shalf * 32);

    // ldmatrix lane address components
    const uint32_t lrow = (uint32_t)(lane & 15);
    const uint32_t lkb  = (uint32_t)((lane >> 4) * 16);

    float acc[4][4][4];   // [mblock][ngroup][reg]
    #pragma unroll
    for (int i = 0; i < 4; i++)
        #pragma unroll
        for (int j = 0; j < 4; j++)
            #pragma unroll
            for (int q = 0; q < 4; q++)
                acc[i][j][q] = 0.0f;

    float4 pa[4];          // prefetched A (16 fp32)
    float4 pbh[2], pbl[2]; // prefetched B hi/lo (16 bf16 each)

    // ---- prologue: load stage 0 ----
    {
        #pragma unroll
        for (int i = 0; i < 4; i++)
            pa[i] = reinterpret_cast<const float4*>(aptr)[i];
        pbh[0] = reinterpret_cast<const float4*>(bptr_h)[0];
        pbh[1] = reinterpret_cast<const float4*>(bptr_h)[1];
        pbl[0] = reinterpret_cast<const float4*>(bptr_l)[0];
        pbl[1] = reinterpret_cast<const float4*>(bptr_l)[1];
    }

    // write helper lambda-free macro-ish: do inline each time
    #pragma unroll 1
    for (int ch = 0; ch < 16; ch++) {
        char* stage = smem + (ch & 1) * STAGE_SZ;
        // ---- write prefetched regs -> smem(stage ch) ----
        {
            const float* f = reinterpret_cast<const float*>(pa);
            uint32_t hw[8], lw[8];
            #pragma unroll
            for (int i = 0; i < 8; i++) {
                float f0 = f[2 * i], f1 = f[2 * i + 1];
                __nv_bfloat162 h2 = __floats2bfloat162_rn(f0, f1);
                float2 hf = __bfloat1622float2(h2);
                __nv_bfloat162 l2 = __floats2bfloat162_rn(f0 - hf.x, f1 - hf.y);
                hw[i] = *reinterpret_cast<uint32_t*>(&h2);
                lw[i] = *reinterpret_cast<uint32_t*>(&l2);
            }
            *reinterpret_cast<uint4*>(stage + OFF_AHI + swoff) =
                make_uint4(hw[0], hw[1], hw[2], hw[3]);
            *reinterpret_cast<uint4*>(stage + OFF_AHI + swoff + 16) =
                make_uint4(hw[4], hw[5], hw[6], hw[7]);
            *reinterpret_cast<uint4*>(stage + OFF_ALO + swoff) =
                make_uint4(lw[0], lw[1], lw[2], lw[3]);
            *reinterpret_cast<uint4*>(stage + OFF_ALO + swoff + 16) =
                make_uint4(lw[4], lw[5], lw[6], lw[7]);
            *reinterpret_cast<float4*>(stage + OFF_BHI + swoff)      = pbh[0];
            *reinterpret_cast<float4*>(stage + OFF_BHI + swoff + 16) = pbh[1];
            *reinterpret_cast<float4*>(stage + OFF_BLO + swoff)      = pbl[0];
            *reinterpret_cast<float4*>(stage + OFF_BLO + swoff + 16) = pbl[1];
        }
        __syncthreads();

        // ---- issue next stage's gmem loads ----
        if (ch < 15) {
            const int koff = (ch + 1) * 32;
            #pragma unroll
            for (int i = 0; i < 4; i++)
                pa[i] = reinterpret_cast<const float4*>(aptr + koff)[i];
            pbh[0] = reinterpret_cast<const float4*>(bptr_h + koff)[0];
            pbh[1] = reinterpret_cast<const float4*>(bptr_h + koff)[1];
            pbl[0] = reinterpret_cast<const float4*>(bptr_l + koff)[0];
            pbl[1] = reinterpret_cast<const float4*>(bptr_l + koff)[1];
        }

        // ---- compute this stage ----
        const uint32_t st = sb + (ch & 1) * STAGE_SZ;
        #pragma unroll
        for (int kk = 0; kk < 2; kk++) {
            const uint32_t kb = (uint32_t)(kk * 32) + lkb;
            uint32_t ahi[4][4], alo[4][4];
            uint32_t bhi[4][2], blo[4][2];
            #pragma unroll
            for (int mb = 0; mb < 4; mb++) {
                uint32_t addr = st + OFF_AHI +
                                (uint32_t)((wm + mb * 16 + lrow) * ROWB) + kb;
                ldm_x4(ahi[mb], addr);
                ldm_x4(alo[mb], addr + (OFF_ALO - OFF_AHI));
            }
            #pragma unroll
            for (int nb = 0; nb < 2; nb++) {
                uint32_t addr = st + OFF_BHI +
                                (uint32_t)((wn + nb * 16 + lrow) * ROWB) + kb;
                uint32_t r[4];
                ldm_x4(r, addr);
                bhi[2 * nb][0] = r[0]; bhi[2 * nb + 1][0] = r[1];
                bhi[2 * nb][1] = r[2]; bhi[2 * nb + 1][1] = r[3];
                ldm_x4(r, addr + (OFF_BLO - OFF_BHI));
                blo[2 * nb][0] = r[0]; blo[2 * nb + 1][0] = r[1];
                blo[2 * nb][1] = r[2]; blo[2 * nb + 1][1] = r[3];
            }
            #pragma unroll
            for (int mb = 0; mb < 4; mb++)
                #pragma unroll
                for (int ng = 0; ng < 4; ng++) {
                    mma_bf16(acc[mb][ng], ahi[mb], bhi[ng]);
                    mma_bf16(acc[mb][ng], ahi[mb], blo[ng]);
                    mma_bf16(acc[mb][ng], alo[mb], bhi[ng]);
                }
        }
        __syncthreads();
    }

    // ---- epilogue: acc regs -> C ----
    {
        const int g = lane >> 2;       // 0..7
        const int tg = lane & 3;       // 0..3
        #pragma unroll
        for (int mb = 0; mb < 4; mb++) {
            const int row0 = bm + wm + mb * 16 + g;
            #pragma unroll
            for (int ng = 0; ng < 4; ng++) {
                const int col = bn + wn + ng * 8 + tg * 2;
                *reinterpret_cast<float2*>(&C[(size_t)row0 * 512 + col]) =
                    make_float2(acc[mb][ng][0], acc[mb][ng][1]);
                *reinterpret_cast<float2*>(&C[(size_t)(row0 + 8) * 512 + col]) =
                    make_float2(acc[mb][ng][2], acc[mb][ng][3]);
            }
        }
    }
}

// ---------------- scan: h_t = relu(xp_t + b + u*h_{t-1}), in-place ----------------
__global__ __launch_bounds__(256) void indrnn_scan(
    float* __restrict__ xp,          // [64, 1024, 512]
    const float* __restrict__ u,     // [512]
    const float* __restrict__ bias)  // [512]
{
    const int T = 1024;
    const int R = 512;
    int idx = blockIdx.x * blockDim.x + threadIdx.x;  // 0..32767
    int b = idx >> 9;
    int r = idx & 511;

    float uu = u[r];
    float bb = bias[r];
    float h = 1.0f;
    float* p = xp + (size_t)b * T * R + r;

    #pragma unroll 1
    for (int t0 = 0; t0 < T; t0 += 16) {
        float v[16];
        #pragma unroll
        for (int j = 0; j < 16; j++)
            v[j] = p[(t0 + j) * R];
        #pragma unroll
        for (int j = 0; j < 16; j++) {
            h = fmaxf(fmaf(uu, h, v[j] + bb), 0.0f);
            v[j] = h;
        }
        #pragma unroll
        for (int j = 0; j < 16; j++)
            p[(t0 + j) * R] = v[j];
    }
}

// ---------------- launch ----------------
extern "C" void kernel_launch(void* const* d_in, const int* in_sizes, int n_in,
                              void* d_out, int out_size)
{
    const float* x  = (const float*)d_in[0];  // [64,1024,512]
    const float* W  = (const float*)d_in[1];  // [512,512]
    const float* u  = (const float*)d_in[2];  // [512]
    const float* b  = (const float*)d_in[3];  // [512]
    float* out = (float*)d_out;               // [64,1024,512]

    (void)in_sizes; (void)n_in; (void)out_size;

    cudaFuncSetAttribute(indrnn_gemm_mma,
                         cudaFuncAttributeMaxDynamicSharedMemorySize, GEMM_SMEM);

    conv_w<<<1024, 256>>>(W);

    dim3 ggrid(4, 512);  // x = n-tile (fastest -> A L2 reuse), y = m-tile
    indrnn_gemm_mma<<<ggrid, 256, GEMM_SMEM>>>(x, out);

    indrnn_scan<<<128, 256>>>(out, u, b);
}

// round 7
// speedup vs baseline: 1.8176x; 1.1691x over previous
#include <cuda_runtime.h>
#include <cuda_bf16.h>
#include <cstdint>

// ============================================================
// IndRNN on GB300 (base-PTX tensor path):
//   xp = x @ W     -> split-bf16 mma.sync (HMMA) GEMM, fp32 accum
//                     3 terms: Ahi*Whi + Ahi*Wlo + Alo*Whi
//   out = scan(relu(xp_t + b + u*h))
// CTA tile 128x256, warp tile 64x64, BK=32, double-buffered,
// cp.async for B, one __syncthreads per stage.
// ============================================================

// Transposed + hi/lo split W scratch ([n][k], k contiguous)
__device__ __nv_bfloat16 g_Wt_hi[512 * 512];
__device__ __nv_bfloat16 g_Wt_lo[512 * 512];

__device__ __forceinline__ uint32_t smem_u32(const void* p) {
    uint32_t a;
    asm("{ .reg .u64 t; cvta.to.shared.u64 t, %1; cvt.u32.u64 %0, t; }"
        : "=r"(a) : "l"(p));
    return a;
}

__device__ __forceinline__ void ldm_x4(uint32_t r[4], uint32_t addr) {
    asm volatile("ldmatrix.sync.aligned.m8n8.x4.shared.b16 {%0,%1,%2,%3}, [%4];"
                 : "=r"(r[0]), "=r"(r[1]), "=r"(r[2]), "=r"(r[3]) : "r"(addr));
}

__device__ __forceinline__ void mma_bf16(float c[4], const uint32_t a[4],
                                         const uint32_t b0, const uint32_t b1) {
    asm volatile(
        "mma.sync.aligned.m16n8k16.row.col.f32.bf16.bf16.f32 "
        "{%0,%1,%2,%3}, {%4,%5,%6,%7}, {%8,%9}, {%0,%1,%2,%3};"
        : "+f"(c[0]), "+f"(c[1]), "+f"(c[2]), "+f"(c[3])
        : "r"(a[0]), "r"(a[1]), "r"(a[2]), "r"(a[3]), "r"(b0), "r"(b1));
}

__device__ __forceinline__ void cp16(uint32_t saddr, const void* g) {
    asm volatile("cp.async.cg.shared.global [%0], [%1], 16;"
                 :: "r"(saddr), "l"(g) : "memory");
}
__device__ __forceinline__ void cp_commit() {
    asm volatile("cp.async.commit_group;" ::: "memory");
}
__device__ __forceinline__ void cp_wait0() {
    asm volatile("cp.async.wait_group 0;" ::: "memory");
}

// ---------------- W prepass: transpose + hi/lo split ----------------
__global__ __launch_bounds__(256) void conv_w(const float* __restrict__ W) {
    int idx = blockIdx.x * blockDim.x + threadIdx.x;  // 0..262143
    int n = idx >> 9;
    int k = idx & 511;
    float w = W[k * 512 + n];
    __nv_bfloat16 h = __float2bfloat16(w);
    g_Wt_hi[idx] = h;
    g_Wt_lo[idx] = __float2bfloat16(w - __bfloat162float(h));
}

// ---------------- HMMA GEMM: C[65536,512] = A[65536,512] @ W ----------------
#define ROWB      80                      // bytes per smem row (32 bf16 + pad)
#define A_MAT     (128 * ROWB)            // 10240
#define B_MAT     (256 * ROWB)            // 20480
#define OFF_AHI   0
#define OFF_ALO   A_MAT                   // 10240
#define OFF_BHI   (2 * A_MAT)             // 20480
#define OFF_BLO   (2 * A_MAT + B_MAT)     // 40960
#define STAGE_SZ  (2 * A_MAT + 2 * B_MAT) // 61440
#define GEMM_SMEM (2 * STAGE_SZ)          // 122880

__global__ __launch_bounds__(256, 1) void indrnn_gemm_mma(
    const float* __restrict__ A,   // [65536, 512]
    float* __restrict__ C)         // [65536, 512]
{
    extern __shared__ char smem[];
    const uint32_t sb = smem_u32(smem);
    const int tid = (int)threadIdx.x;
    const int wid = tid >> 5;
    const int lane = tid & 31;

    const int bn = blockIdx.x * 256;   // 2 n-tiles
    const int bm = blockIdx.y * 128;   // 512 m-tiles

    const int wm = (wid & 1) * 64;     // warp m-offset
    const int wn = (wid >> 1) * 64;    // warp n-offset

    // A staging: thread owns 16 consecutive k of one row
    const int srow = tid >> 1;         // 0..127
    const int sh   = tid & 1;          // k half
    const float* aptr = A + (size_t)(bm + srow) * 512 + sh * 16;
    const uint32_t aswoff = (uint32_t)(srow * ROWB + sh * 32);

    // B staging via cp.async: thread owns one n-row, 4x16B chunks
    const __nv_bfloat16* bgp_h = g_Wt_hi + (size_t)(bn + tid) * 512;
    const __nv_bfloat16* bgp_l = g_Wt_lo + (size_t)(bn + tid) * 512;
    const uint32_t bswrow = (uint32_t)(tid * ROWB);

    // ldmatrix lane address components
    const uint32_t lrow = (uint32_t)(lane & 15);
    const uint32_t lkb  = (uint32_t)((lane >> 4) * 16);

    float acc[4][8][4];   // [mblock][ngroup][reg] = 128 regs
    #pragma unroll
    for (int i = 0; i < 4; i++)
        #pragma unroll
        for (int j = 0; j < 8; j++)
            #pragma unroll
            for (int q = 0; q < 4; q++)
                acc[i][j][q] = 0.0f;

    float4 pa[4];  // A prefetch regs (16 fp32)

    // ---- prologue: stage 0 ----
    {
        #pragma unroll
        for (int c = 0; c < 4; c++) {
            cp16(sb + OFF_BHI + bswrow + c * 16, bgp_h + c * 8);
            cp16(sb + OFF_BLO + bswrow + c * 16, bgp_l + c * 8);
        }
        cp_commit();
        #pragma unroll
        for (int i = 0; i < 4; i++)
            pa[i] = reinterpret_cast<const float4*>(aptr)[i];
        // convert + store A stage 0
        const float* f = reinterpret_cast<const float*>(pa);
        uint32_t hw[8], lw[8];
        #pragma unroll
        for (int i = 0; i < 8; i++) {
            float f0 = f[2 * i], f1 = f[2 * i + 1];
            __nv_bfloat162 h2 = __floats2bfloat162_rn(f0, f1);
            float2 hf = __bfloat1622float2(h2);
            __nv_bfloat162 l2 = __floats2bfloat162_rn(f0 - hf.x, f1 - hf.y);
            hw[i] = *reinterpret_cast<uint32_t*>(&h2);
            lw[i] = *reinterpret_cast<uint32_t*>(&l2);
        }
        char* stage = smem;
        *reinterpret_cast<uint4*>(stage + OFF_AHI + aswoff) =
            make_uint4(hw[0], hw[1], hw[2], hw[3]);
        *reinterpret_cast<uint4*>(stage + OFF_AHI + aswoff + 16) =
            make_uint4(hw[4], hw[5], hw[6], hw[7]);
        *reinterpret_cast<uint4*>(stage + OFF_ALO + aswoff) =
            make_uint4(lw[0], lw[1], lw[2], lw[3]);
        *reinterpret_cast<uint4*>(stage + OFF_ALO + aswoff + 16) =
            make_uint4(lw[4], lw[5], lw[6], lw[7]);
        cp_wait0();
    }
    __syncthreads();

    #pragma unroll 1
    for (int ch = 0; ch < 16; ch++) {
        const uint32_t st = sb + (uint32_t)(ch & 1) * STAGE_SZ;
        const uint32_t nstb = sb + (uint32_t)((ch + 1) & 1) * STAGE_SZ;

        // ---- issue next stage's loads (cp.async B, LDG A) ----
        if (ch < 15) {
            const int koff = (ch + 1) * 32;
            #pragma unroll
            for (int c = 0; c < 4; c++) {
                cp16(nstb + OFF_BHI + bswrow + c * 16, bgp_h + koff + c * 8);
                cp16(nstb + OFF_BLO + bswrow + c * 16, bgp_l + koff + c * 8);
            }
            cp_commit();
            #pragma unroll
            for (int i = 0; i < 4; i++)
                pa[i] = reinterpret_cast<const float4*>(aptr + koff)[i];
        }

        // ---- compute this stage ----
        #pragma unroll
        for (int kk = 0; kk < 2; kk++) {
            const uint32_t kb = (uint32_t)(kk * 32) + lkb;
            uint32_t am[4][4];     // A fragment (hi, later reused for lo)
            uint32_t bh[8][2];     // B hi fragments (stay live)

            // phase 1: Ahi * Bhi
            #pragma unroll
            for (int mb = 0; mb < 4; mb++)
                ldm_x4(am[mb], st + OFF_AHI +
                               (uint32_t)((wm + mb * 16 + lrow) * ROWB) + kb);
            #pragma unroll
            for (int nb = 0; nb < 4; nb++) {
                uint32_t r[4];
                ldm_x4(r, st + OFF_BHI +
                          (uint32_t)((wn + nb * 16 + lrow) * ROWB) + kb);
                bh[2 * nb][0] = r[0]; bh[2 * nb + 1][0] = r[1];
                bh[2 * nb][1] = r[2]; bh[2 * nb + 1][1] = r[3];
            }
            #pragma unroll
            for (int mb = 0; mb < 4; mb++)
                #pragma unroll
                for (int ng = 0; ng < 8; ng++)
                    mma_bf16(acc[mb][ng], am[mb], bh[ng][0], bh[ng][1]);

            // phase 2: Ahi * Blo
            #pragma unroll
            for (int nb = 0; nb < 4; nb++) {
                uint32_t r[4];
                ldm_x4(r, st + OFF_BLO +
                          (uint32_t)((wn + nb * 16 + lrow) * ROWB) + kb);
                uint32_t b0a = r[0], b1a = r[2];
                uint32_t b0b = r[1], b1b = r[3];
                #pragma unroll
                for (int mb = 0; mb < 4; mb++) {
                    mma_bf16(acc[mb][2 * nb], am[mb], b0a, b1a);
                    mma_bf16(acc[mb][2 * nb + 1], am[mb], b0b, b1b);
                }
            }

            // phase 3: Alo * Bhi
            #pragma unroll
            for (int mb = 0; mb < 4; mb++) {
                ldm_x4(am[mb], st + OFF_ALO +
                               (uint32_t)((wm + mb * 16 + lrow) * ROWB) + kb);
                #pragma unroll
                for (int ng = 0; ng < 8; ng++)
                    mma_bf16(acc[mb][ng], am[mb], bh[ng][0], bh[ng][1]);
            }
        }

        // ---- convert + store next A stage ----
        if (ch < 15) {
            const float* f = reinterpret_cast<const float*>(pa);
            uint32_t hw[8], lw[8];
            #pragma unroll
            for (int i = 0; i < 8; i++) {
                float f0 = f[2 * i], f1 = f[2 * i + 1];
                __nv_bfloat162 h2 = __floats2bfloat162_rn(f0, f1);
                float2 hf = __bfloat1622float2(h2);
                __nv_bfloat162 l2 = __floats2bfloat162_rn(f0 - hf.x, f1 - hf.y);
                hw[i] = *reinterpret_cast<uint32_t*>(&h2);
                lw[i] = *reinterpret_cast<uint32_t*>(&l2);
            }
            char* nst = smem + ((ch + 1) & 1) * STAGE_SZ;
            *reinterpret_cast<uint4*>(nst + OFF_AHI + aswoff) =
                make_uint4(hw[0], hw[1], hw[2], hw[3]);
            *reinterpret_cast<uint4*>(nst + OFF_AHI + aswoff + 16) =
                make_uint4(hw[4], hw[5], hw[6], hw[7]);
            *reinterpret_cast<uint4*>(nst + OFF_ALO + aswoff) =
                make_uint4(lw[0], lw[1], lw[2], lw[3]);
            *reinterpret_cast<uint4*>(nst + OFF_ALO + aswoff + 16) =
                make_uint4(lw[4], lw[5], lw[6], lw[7]);
            cp_wait0();
        }
        __syncthreads();
    }

    // ---- epilogue: acc regs -> C ----
    {
        const int g = lane >> 2;       // 0..7
        const int tg = lane & 3;       // 0..3
        #pragma unroll
        for (int mb = 0; mb < 4; mb++) {
            const int row0 = bm + wm + mb * 16 + g;
            #pragma unroll
            for (int ng = 0; ng < 8; ng++) {
                const int col = bn + wn + ng * 8 + tg * 2;
                *reinterpret_cast<float2*>(&C[(size_t)row0 * 512 + col]) =
                    make_float2(acc[mb][ng][0], acc[mb][ng][1]);
                *reinterpret_cast<float2*>(&C[(size_t)(row0 + 8) * 512 + col]) =
                    make_float2(acc[mb][ng][2], acc[mb][ng][3]);
            }
        }
    }
}

// ---------------- scan: h_t = relu(xp_t + b + u*h_{t-1}), in-place ----------------
__global__ __launch_bounds__(256) void indrnn_scan(
    float* __restrict__ xp,          // [64, 1024, 512]
    const float* __restrict__ u,     // [512]
    const float* __restrict__ bias)  // [512]
{
    const int T = 1024;
    const int R = 512;
    int idx = blockIdx.x * blockDim.x + threadIdx.x;  // 0..32767
    int b = idx >> 9;
    int r = idx & 511;

    float uu = u[r];
    float bb = bias[r];
    float h = 1.0f;
    float* p = xp + (size_t)b * T * R + r;

    #pragma unroll 1
    for (int t0 = 0; t0 < T; t0 += 32) {
        float v[32];
        #pragma unroll
        for (int j = 0; j < 32; j++)
            v[j] = p[(t0 + j) * R];
        #pragma unroll
        for (int j = 0; j < 32; j++) {
            h = fmaxf(fmaf(uu, h, v[j] + bb), 0.0f);
            v[j] = h;
        }
        #pragma unroll
        for (int j = 0; j < 32; j++)
            p[(t0 + j) * R] = v[j];
    }
}

// ---------------- launch ----------------
extern "C" void kernel_launch(void* const* d_in, const int* in_sizes, int n_in,
                              void* d_out, int out_size)
{
    const float* x  = (const float*)d_in[0];  // [64,1024,512]
    const float* W  = (const float*)d_in[1];  // [512,512]
    const float* u  = (const float*)d_in[2];  // [512]
    const float* b  = (const float*)d_in[3];  // [512]
    float* out = (float*)d_out;               // [64,1024,512]

    (void)in_sizes; (void)n_in; (void)out_size;

    cudaFuncSetAttribute(indrnn_gemm_mma,
                         cudaFuncAttributeMaxDynamicSharedMemorySize, GEMM_SMEM);

    conv_w<<<1024, 256>>>(W);

    dim3 ggrid(2, 512);  // x = n-tile, y = m-tile
    indrnn_gemm_mma<<<ggrid, 256, GEMM_SMEM>>>(x, out);

    indrnn_scan<<<128, 256>>>(out, u, b);
}

// round 9
// speedup vs baseline: 2.2697x; 1.2487x over previous
#include <cuda_runtime.h>
#include <cuda_bf16.h>
#include <cstdint>

// ============================================================
// IndRNN on GB300 (base-PTX tensor path):
//   xp = x @ W     -> single-pass TF32 mma.sync (m16n8k8), fp32 accum
//   out = scan(relu(xp_t + b + u*h))
// CTA tile 128x256, warp tile 64x64, BK=32, double-buffered smem,
// cp.async for W (pre-transposed + tf32-rounded), rna-rounded A.
// R9 fix: fragment loads via proper smem generic pointers (R8 read
// through raw cvta'd shared addresses as generic -> garbage).
// ============================================================

// Transposed, tf32-rounded W scratch: g_Wt[n][k], fp32 bits
__device__ float g_Wt[512 * 512];

__device__ __forceinline__ uint32_t smem_u32(const void* p) {
    uint32_t a;
    asm("{ .reg .u64 t; cvta.to.shared.u64 t, %1; cvt.u32.u64 %0, t; }"
        : "=r"(a) : "l"(p));
    return a;
}

__device__ __forceinline__ uint32_t f2tf32(float f) {
    uint32_t r;
    asm("cvt.rna.tf32.f32 %0, %1;" : "=r"(r) : "f"(f));
    return r;
}

__device__ __forceinline__ void mma_tf32(float c[4], const uint32_t a[4],
                                         const uint32_t b0, const uint32_t b1) {
    asm volatile(
        "mma.sync.aligned.m16n8k8.row.col.f32.tf32.tf32.f32 "
        "{%0,%1,%2,%3}, {%4,%5,%6,%7}, {%8,%9}, {%0,%1,%2,%3};"
        : "+f"(c[0]), "+f"(c[1]), "+f"(c[2]), "+f"(c[3])
        : "r"(a[0]), "r"(a[1]), "r"(a[2]), "r"(a[3]), "r"(b0), "r"(b1));
}

__device__ __forceinline__ void cp16(uint32_t saddr, const void* g) {
    asm volatile("cp.async.cg.shared.global [%0], [%1], 16;"
                 :: "r"(saddr), "l"(g) : "memory");
}
__device__ __forceinline__ void cp_commit() {
    asm volatile("cp.async.commit_group;" ::: "memory");
}
__device__ __forceinline__ void cp_wait0() {
    asm volatile("cp.async.wait_group 0;" ::: "memory");
}

// ---------------- W prepass: transpose + tf32 round ----------------
__global__ __launch_bounds__(256) void conv_w(const float* __restrict__ W) {
    int idx = blockIdx.x * blockDim.x + threadIdx.x;  // 0..262143
    int n = idx >> 9;
    int k = idx & 511;
    uint32_t v = f2tf32(W[k * 512 + n]);
    g_Wt[idx] = __uint_as_float(v);
}

// ---------------- TF32 GEMM: C[65536,512] = A[65536,512] @ W ----------------
// smem rows padded: 32 floats data + 4 pad = 36 words = 144 B -> conflict-free
#define ROWW      36                      // words per smem row
#define ROWBYTES  144
#define A_MAT     (128 * ROWBYTES)        // 18432
#define B_MAT     (256 * ROWBYTES)        // 36864
#define OFF_A     0
#define OFF_B     A_MAT
#define STAGE_SZ  (A_MAT + B_MAT)         // 55296
#define GEMM_SMEM (2 * STAGE_SZ)          // 110592

__global__ __launch_bounds__(256, 1) void indrnn_gemm_tf32(
    const float* __restrict__ A,   // [65536, 512]
    float* __restrict__ C)         // [65536, 512]
{
    extern __shared__ char smem[];
    const uint32_t sb = smem_u32(smem);
    const int tid = (int)threadIdx.x;
    const int wid = tid >> 5;
    const int lane = tid & 31;

    const int bn = blockIdx.x * 256;   // 2 n-tiles (W stays L2-resident)
    const int bm = blockIdx.y * 128;   // 512 m-tiles

    const int wm = (wid & 1) * 64;     // warp m-offset
    const int wn = (wid >> 1) * 64;    // warp n-offset

    const int grp = lane >> 2;         // 0..7
    const int tg  = lane & 3;          // 0..3

    // A staging: thread owns 16 consecutive k of one row
    const int srow = tid >> 1;         // 0..127
    const int sh   = tid & 1;
    const float* aptr = A + (size_t)(bm + srow) * 512 + sh * 16;
    const uint32_t aswoff = (uint32_t)(srow * ROWBYTES + sh * 64);

    // B staging via cp.async: thread owns one n-row (32 floats = 8x16B)
    const float* bgp = g_Wt + (size_t)(bn + tid) * 512;
    const uint32_t bswrow = (uint32_t)(tid * ROWBYTES);

    float acc[4][8][4];   // [mblock][ngroup][reg] = 128 regs
    #pragma unroll
    for (int i = 0; i < 4; i++)
        #pragma unroll
        for (int j = 0; j < 8; j++)
            #pragma unroll
            for (int q = 0; q < 4; q++)
                acc[i][j][q] = 0.0f;

    float4 pa[4];  // A prefetch regs (16 fp32)

    // ---- prologue: stage 0 ----
    {
        #pragma unroll
        for (int c = 0; c < 8; c++)
            cp16(sb + OFF_B + bswrow + c * 16, bgp + c * 4);
        cp_commit();
        #pragma unroll
        for (int i = 0; i < 4; i++)
            pa[i] = reinterpret_cast<const float4*>(aptr)[i];
        const float* f = reinterpret_cast<const float*>(pa);
        #pragma unroll
        for (int c = 0; c < 4; c++) {
            uint4 v = make_uint4(f2tf32(f[4 * c]), f2tf32(f[4 * c + 1]),
                                 f2tf32(f[4 * c + 2]), f2tf32(f[4 * c + 3]));
            *reinterpret_cast<uint4*>(smem + OFF_A + aswoff + c * 16) = v;
        }
        cp_wait0();
    }
    __syncthreads();

    #pragma unroll 1
    for (int ch = 0; ch < 16; ch++) {
        const char* stc = smem + (ch & 1) * STAGE_SZ;
        const uint32_t nstb = sb + (uint32_t)((ch + 1) & 1) * STAGE_SZ;

        // ---- issue next stage's loads ----
        if (ch < 15) {
            const int koff = (ch + 1) * 32;
            #pragma unroll
            for (int c = 0; c < 8; c++)
                cp16(nstb + OFF_B + bswrow + c * 16, bgp + koff + c * 4);
            cp_commit();
            #pragma unroll
            for (int i = 0; i < 4; i++)
                pa[i] = reinterpret_cast<const float4*>(aptr + koff)[i];
        }

        // ---- compute this stage: 4 k8-steps ----
        const float* abase = reinterpret_cast<const float*>(stc + OFF_A);
        const float* bbase = reinterpret_cast<const float*>(stc + OFF_B);
        #pragma unroll
        for (int ks = 0; ks < 4; ks++) {
            const int k0 = ks * 8;
            uint32_t am[4][4];
            uint32_t bf[8][2];

            #pragma unroll
            for (int mb = 0; mb < 4; mb++) {
                const float* ar = abase + (wm + mb * 16 + grp) * ROWW + k0 + tg;
                am[mb][0] = __float_as_uint(ar[0]);
                am[mb][1] = __float_as_uint(ar[8 * ROWW]);
                am[mb][2] = __float_as_uint(ar[4]);
                am[mb][3] = __float_as_uint(ar[8 * ROWW + 4]);
            }
            #pragma unroll
            for (int ng = 0; ng < 8; ng++) {
                const float* br = bbase + (wn + ng * 8 + grp) * ROWW + k0 + tg;
                bf[ng][0] = __float_as_uint(br[0]);
                bf[ng][1] = __float_as_uint(br[4]);
            }
            #pragma unroll
            for (int mb = 0; mb < 4; mb++)
                #pragma unroll
                for (int ng = 0; ng < 8; ng++)
                    mma_tf32(acc[mb][ng], am[mb], bf[ng][0], bf[ng][1]);
        }

        // ---- convert + store next A stage ----
        if (ch < 15) {
            const float* f = reinterpret_cast<const float*>(pa);
            char* nst = smem + ((ch + 1) & 1) * STAGE_SZ;
            #pragma unroll
            for (int c = 0; c < 4; c++) {
                uint4 v = make_uint4(f2tf32(f[4 * c]), f2tf32(f[4 * c + 1]),
                                     f2tf32(f[4 * c + 2]), f2tf32(f[4 * c + 3]));
                *reinterpret_cast<uint4*>(nst + OFF_A + aswoff + c * 16) = v;
            }
            cp_wait0();
        }
        __syncthreads();
    }

    // ---- epilogue: acc regs -> C ----
    {
        #pragma unroll
        for (int mb = 0; mb < 4; mb++) {
            const int row0 = bm + wm + mb * 16 + grp;
            #pragma unroll
            for (int ng = 0; ng < 8; ng++) {
                const int col = bn + wn + ng * 8 + tg * 2;
                *reinterpret_cast<float2*>(&C[(size_t)row0 * 512 + col]) =
                    make_float2(acc[mb][ng][0], acc[mb][ng][1]);
                *reinterpret_cast<float2*>(&C[(size_t)(row0 + 8) * 512 + col]) =
                    make_float2(acc[mb][ng][2], acc[mb][ng][3]);
            }
        }
    }
}

// ---------------- scan: h_t = relu(xp_t + b + u*h_{t-1}), in-place ----------------
__global__ __launch_bounds__(256) void indrnn_scan(
    float* __restrict__ xp,          // [64, 1024, 512]
    const float* __restrict__ u,     // [512]
    const float* __restrict__ bias)  // [512]
{
    const int T = 1024;
    const int R = 512;
    int idx = blockIdx.x * blockDim.x + threadIdx.x;  // 0..32767
    int b = idx >> 9;
    int r = idx & 511;

    float uu = u[r];
    float bb = bias[r];
    float h = 1.0f;
    float* p = xp + (size_t)b * T * R + r;

    #pragma unroll 1
    for (int t0 = 0; t0 < T; t0 += 32) {
        float v[32];
        #pragma unroll
        for (int j = 0; j < 32; j++)
            v[j] = p[(t0 + j) * R];
        #pragma unroll
        for (int j = 0; j < 32; j++) {
            h = fmaxf(fmaf(uu, h, v[j] + bb), 0.0f);
            v[j] = h;
        }
        #pragma unroll
        for (int j = 0; j < 32; j++)
            p[(t0 + j) * R] = v[j];
    }
}

// ---------------- launch ----------------
extern "C" void kernel_launch(void* const* d_in, const int* in_sizes, int n_in,
                              void* d_out, int out_size)
{
    const float* x  = (const float*)d_in[0];  // [64,1024,512]
    const float* W  = (const float*)d_in[1];  // [512,512]
    const float* u  = (const float*)d_in[2];  // [512]
    const float* b  = (const float*)d_in[3];  // [512]
    float* out = (float*)d_out;               // [64,1024,512]

    (void)in_sizes; (void)n_in; (void)out_size;

    cudaFuncSetAttribute(indrnn_gemm_tf32,
                         cudaFuncAttributeMaxDynamicSharedMemorySize, GEMM_SMEM);

    conv_w<<<1024, 256>>>(W);

    dim3 ggrid(2, 512);  // x = n-tile, y = m-tile
    indrnn_gemm_tf32<<<ggrid, 256, GEMM_SMEM>>>(x, out);

    indrnn_scan<<<128, 256>>>(out, u, b);
}

// round 10
// speedup vs baseline: 3.3135x; 1.4599x over previous
#include <cuda_runtime.h>
#include <cuda_fp16.h>
#include <cstdint>

// ============================================================
// IndRNN on GB300 (base-PTX tensor path):
//   xp = x @ W     -> single-pass FP16 mma.sync (m16n8k16), fp32 accum
//                     (fp16 significand == tf32 significand: same accuracy,
//                      half the mma instructions of the tf32 k8 path)
//   out = scan(relu(xp_t + b + u*h))
// CTA tile 128x256, warp tile 64x64, BK=32, double-buffered smem,
// cp.async for W (pre-transposed fp16), inline fp32->fp16 for A,
// ldmatrix fragment loads (80B padded rows, conflict-free).
// ============================================================

// Transposed fp16 W scratch: g_Wt[n][k]
__device__ __half g_Wt[512 * 512];

__device__ __forceinline__ uint32_t smem_u32(const void* p) {
    uint32_t a;
    asm("{ .reg .u64 t; cvta.to.shared.u64 t, %1; cvt.u32.u64 %0, t; }"
        : "=r"(a) : "l"(p));
    return a;
}

__device__ __forceinline__ void ldm_x4(uint32_t r[4], uint32_t addr) {
    asm volatile("ldmatrix.sync.aligned.m8n8.x4.shared.b16 {%0,%1,%2,%3}, [%4];"
                 : "=r"(r[0]), "=r"(r[1]), "=r"(r[2]), "=r"(r[3]) : "r"(addr));
}

__device__ __forceinline__ void mma_f16(float c[4], const uint32_t a[4],
                                        const uint32_t b0, const uint32_t b1) {
    asm volatile(
        "mma.sync.aligned.m16n8k16.row.col.f32.f16.f16.f32 "
        "{%0,%1,%2,%3}, {%4,%5,%6,%7}, {%8,%9}, {%0,%1,%2,%3};"
        : "+f"(c[0]), "+f"(c[1]), "+f"(c[2]), "+f"(c[3])
        : "r"(a[0]), "r"(a[1]), "r"(a[2]), "r"(a[3]), "r"(b0), "r"(b1));
}

__device__ __forceinline__ void cp16(uint32_t saddr, const void* g) {
    asm volatile("cp.async.cg.shared.global [%0], [%1], 16;"
                 :: "r"(saddr), "l"(g) : "memory");
}
__device__ __forceinline__ void cp_commit() {
    asm volatile("cp.async.commit_group;" ::: "memory");
}
__device__ __forceinline__ void cp_wait0() {
    asm volatile("cp.async.wait_group 0;" ::: "memory");
}

__device__ __forceinline__ uint32_t h2_bits(__half2 v) {
    return *reinterpret_cast<uint32_t*>(&v);
}

// ---------------- W prepass: transpose + fp16 round ----------------
__global__ __launch_bounds__(256) void conv_w(const float* __restrict__ W) {
    int idx = blockIdx.x * blockDim.x + threadIdx.x;  // 0..262143
    int n = idx >> 9;
    int k = idx & 511;
    g_Wt[idx] = __float2half_rn(W[k * 512 + n]);
}

// ---------------- FP16 GEMM: C[65536,512] = A[65536,512] @ W ----------------
// smem rows: 32 halves (64B) + 16B pad = 80B -> conflict-free ldmatrix
#define ROWB      80
#define A_MAT     (128 * ROWB)            // 10240
#define B_MAT     (256 * ROWB)            // 20480
#define OFF_A     0
#define OFF_B     A_MAT
#define STAGE_SZ  (A_MAT + B_MAT)         // 30720
#define GEMM_SMEM (2 * STAGE_SZ)          // 61440

__global__ __launch_bounds__(256, 1) void indrnn_gemm_f16(
    const float* __restrict__ A,   // [65536, 512]
    float* __restrict__ C)         // [65536, 512]
{
    extern __shared__ char smem[];
    const uint32_t sb = smem_u32(smem);
    const int tid = (int)threadIdx.x;
    const int wid = tid >> 5;
    const int lane = tid & 31;

    const int bn = blockIdx.x * 256;   // 2 n-tiles (W stays L2-resident)
    const int bm = blockIdx.y * 128;   // 512 m-tiles

    const int wm = (wid & 1) * 64;     // warp m-offset
    const int wn = (wid >> 1) * 64;    // warp n-offset

    const int grp = lane >> 2;         // 0..7 (epilogue)
    const int tg  = lane & 3;          // 0..3

    // ldmatrix lane address components
    const uint32_t lrow = (uint32_t)(lane & 15);
    const uint32_t lkb  = (uint32_t)((lane >> 4) * 16);

    // A staging: thread owns 16 consecutive k of one row
    const int srow = tid >> 1;         // 0..127
    const int sh   = tid & 1;
    const float* aptr = A + (size_t)(bm + srow) * 512 + sh * 16;
    const uint32_t aswoff = (uint32_t)(srow * ROWB + sh * 32);

    // B staging via cp.async: thread owns one n-row (32 halves = 4x16B)
    const __half* bgp = g_Wt + (size_t)(bn + tid) * 512;
    const uint32_t bswrow = (uint32_t)(tid * ROWB);

    float acc[4][8][4];   // [mblock][ngroup][reg] = 128 regs
    #pragma unroll
    for (int i = 0; i < 4; i++)
        #pragma unroll
        for (int j = 0; j < 8; j++)
            #pragma unroll
            for (int q = 0; q < 4; q++)
                acc[i][j][q] = 0.0f;

    float4 pa[4];  // A prefetch regs (16 fp32)

    // ---- prologue: stage 0 ----
    {
        #pragma unroll
        for (int c = 0; c < 4; c++)
            cp16(sb + OFF_B + bswrow + c * 16, bgp + c * 8);
        cp_commit();
        #pragma unroll
        for (int i = 0; i < 4; i++)
            pa[i] = reinterpret_cast<const float4*>(aptr)[i];
        const float* f = reinterpret_cast<const float*>(pa);
        uint32_t hw[8];
        #pragma unroll
        for (int i = 0; i < 8; i++)
            hw[i] = h2_bits(__floats2half2_rn(f[2 * i], f[2 * i + 1]));
        *reinterpret_cast<uint4*>(smem + OFF_A + aswoff) =
            make_uint4(hw[0], hw[1], hw[2], hw[3]);
        *reinterpret_cast<uint4*>(smem + OFF_A + aswoff + 16) =
            make_uint4(hw[4], hw[5], hw[6], hw[7]);
        cp_wait0();
    }
    __syncthreads();

    #pragma unroll 1
    for (int ch = 0; ch < 16; ch++) {
        const uint32_t st = sb + (uint32_t)(ch & 1) * STAGE_SZ;
        const uint32_t nstb = sb + (uint32_t)((ch + 1) & 1) * STAGE_SZ;

        // ---- issue next stage's loads ----
        if (ch < 15) {
            const int koff = (ch + 1) * 32;
            #pragma unroll
            for (int c = 0; c < 4; c++)
                cp16(nstb + OFF_B + bswrow + c * 16, bgp + koff + c * 8);
            cp_commit();
            #pragma unroll
            for (int i = 0; i < 4; i++)
                pa[i] = reinterpret_cast<const float4*>(aptr + koff)[i];
        }

        // ---- compute this stage: 2 k16-steps ----
        #pragma unroll
        for (int ks = 0; ks < 2; ks++) {
            const uint32_t kb = (uint32_t)(ks * 32) + lkb;
            uint32_t am[4][4];
            uint32_t bh[8][2];

            #pragma unroll
            for (int mb = 0; mb < 4; mb++)
                ldm_x4(am[mb], st + OFF_A +
                               (uint32_t)((wm + mb * 16 + (int)lrow) * ROWB) + kb);
            #pragma unroll
            for (int nb = 0; nb < 4; nb++) {
                uint32_t r[4];
                ldm_x4(r, st + OFF_B +
                          (uint32_t)((wn + nb * 16 + (int)lrow) * ROWB) + kb);
                bh[2 * nb][0] = r[0]; bh[2 * nb + 1][0] = r[1];
                bh[2 * nb][1] = r[2]; bh[2 * nb + 1][1] = r[3];
            }
            #pragma unroll
            for (int mb = 0; mb < 4; mb++)
                #pragma unroll
                for (int ng = 0; ng < 8; ng++)
                    mma_f16(acc[mb][ng], am[mb], bh[ng][0], bh[ng][1]);
        }

        // ---- convert + store next A stage ----
        if (ch < 15) {
            const float* f = reinterpret_cast<const float*>(pa);
            char* nst = smem + ((ch + 1) & 1) * STAGE_SZ;
            uint32_t hw[8];
            #pragma unroll
            for (int i = 0; i < 8; i++)
                hw[i] = h2_bits(__floats2half2_rn(f[2 * i], f[2 * i + 1]));
            *reinterpret_cast<uint4*>(nst + OFF_A + aswoff) =
                make_uint4(hw[0], hw[1], hw[2], hw[3]);
            *reinterpret_cast<uint4*>(nst + OFF_A + aswoff + 16) =
                make_uint4(hw[4], hw[5], hw[6], hw[7]);
            cp_wait0();
        }
        __syncthreads();
    }

    // ---- epilogue: acc regs -> C ----
    {
        #pragma unroll
        for (int mb = 0; mb < 4; mb++) {
            const int row0 = bm + wm + mb * 16 + grp;
            #pragma unroll
            for (int ng = 0; ng < 8; ng++) {
                const int col = bn + wn + ng * 8 + tg * 2;
                *reinterpret_cast<float2*>(&C[(size_t)row0 * 512 + col]) =
                    make_float2(acc[mb][ng][0], acc[mb][ng][1]);
                *reinterpret_cast<float2*>(&C[(size_t)(row0 + 8) * 512 + col]) =
                    make_float2(acc[mb][ng][2], acc[mb][ng][3]);
            }
        }
    }
}

// ---------------- scan: h_t = relu(xp_t + b + u*h_{t-1}), in-place ----------------
__global__ __launch_bounds__(256) void indrnn_scan(
    float* __restrict__ xp,          // [64, 1024, 512]
    const float* __restrict__ u,     // [512]
    const float* __restrict__ bias)  // [512]
{
    const int T = 1024;
    const int R = 512;
    int idx = blockIdx.x * blockDim.x + threadIdx.x;  // 0..32767
    int b = idx >> 9;
    int r = idx & 511;

    float uu = u[r];
    float bb = bias[r];
    float h = 1.0f;
    float* p = xp + (size_t)b * T * R + r;

    #pragma unroll 1
    for (int t0 = 0; t0 < T; t0 += 32) {
        float v[32];
        #pragma unroll
        for (int j = 0; j < 32; j++)
            v[j] = p[(t0 + j) * R];
        #pragma unroll
        for (int j = 0; j < 32; j++) {
            h = fmaxf(fmaf(uu, h, v[j] + bb), 0.0f);
            v[j] = h;
        }
        #pragma unroll
        for (int j = 0; j < 32; j++)
            p[(t0 + j) * R] = v[j];
    }
}

// ---------------- launch ----------------
extern "C" void kernel_launch(void* const* d_in, const int* in_sizes, int n_in,
                              void* d_out, int out_size)
{
    const float* x  = (const float*)d_in[0];  // [64,1024,512]
    const float* W  = (const float*)d_in[1];  // [512,512]
    const float* u  = (const float*)d_in[2];  // [512]
    const float* b  = (const float*)d_in[3];  // [512]
    float* out = (float*)d_out;               // [64,1024,512]

    (void)in_sizes; (void)n_in; (void)out_size;

    cudaFuncSetAttribute(indrnn_gemm_f16,
                         cudaFuncAttributeMaxDynamicSharedMemorySize, GEMM_SMEM);

    conv_w<<<1024, 256>>>(W);

    dim3 ggrid(2, 512);  // x = n-tile, y = m-tile
    indrnn_gemm_f16<<<ggrid, 256, GEMM_SMEM>>>(x, out);

    indrnn_scan<<<128, 256>>>(out, u, b);
}